// round 14
// baseline (speedup 1.0000x reference)
#include <cuda_runtime.h>
#include <cuda_bf16.h>
#include <math.h>
#include <stdint.h>

#define T_STEPS 32
#define NB      64
#define CDIM    512
#define F1DIM   2048
#define F2DIM   1024
#define F3DIM   512
#define BATCH   (T_STEPS * NB)   // 2048

#define MARGIN 4e-3f             // certified decision margin

// ---------------- scratch (device globals; no allocation allowed) -------------
// trace split planes [3][BATCH][K] + fp32 exact traces
__device__ __align__(16) __nv_bfloat16 g_A1s[3 * BATCH * CDIM];
__device__ __align__(16) __nv_bfloat16 g_A2s[3 * BATCH * F1DIM];
__device__ __align__(16) __nv_bfloat16 g_A3s[3 * BATCH * F2DIM];
__device__ __align__(16) float g_F1[BATCH * CDIM];
__device__ __align__(16) float g_F2[BATCH * F1DIM];
__device__ __align__(16) float g_F3[BATCH * F2DIM];
__device__ __align__(16) float g_U1[BATCH * F1DIM];
__device__ __align__(16) float g_U2[BATCH * F2DIM];
__device__ __align__(16) float g_U3[BATCH * F3DIM];
// weight split planes [3][O][K]
__device__ __align__(16) __nv_bfloat16 g_W1s[3 * F1DIM * CDIM];
__device__ __align__(16) __nv_bfloat16 g_W2s[3 * F2DIM * F1DIM];
__device__ __align__(16) __nv_bfloat16 g_W3s[3 * F3DIM * F2DIM];
// flag lists
__device__ int g_cnt1[NB], g_cnt2[NB], g_cnt3[NB];
__device__ int g_lst1[NB * F1DIM], g_lst2[NB * F2DIM], g_lst3[NB * F3DIM];

__device__ __forceinline__ float sigmoid_acc(float w) {
    return 1.0f / (1.0f + expf(-w));
}
__device__ __forceinline__ void split3(float w, __nv_bfloat16& h,
                                       __nv_bfloat16& m, __nv_bfloat16& l) {
    h = __float2bfloat16(w);
    float r1 = w - __bfloat162float(h);
    m = __float2bfloat16(r1);
    float r2 = r1 - __bfloat162float(m);
    l = __float2bfloat16(r2);
}

__global__ void zero_counts() {
    int i = threadIdx.x;
    if (i < NB) { g_cnt1[i] = 0; g_cnt2[i] = 0; g_cnt3[i] = 0; }
}

// ---------------------------------------------------------------------------
__global__ void split_kernel(const float* __restrict__ W,
                             __nv_bfloat16* __restrict__ dst, int n)
{
    int i = blockIdx.x * blockDim.x + threadIdx.x;
    if (i >= n) return;
    __nv_bfloat16 h, m, l;
    split3(W[i], h, m, l);
    dst[i] = h; dst[n + i] = m; dst[2 * n + i] = l;
}

// ---------------------------------------------------------------------------
// Stage 1 (R1-exact math) -> trace f1 fp32 + split planes
// ---------------------------------------------------------------------------
__global__ void stage1_kernel(const float* __restrict__ x,
                              const float* __restrict__ w_jeff,
                              const float* __restrict__ w_cc,
                              const float* __restrict__ w_sf0,
                              const float* __restrict__ w_sf1)
{
    int gw   = (blockIdx.x * blockDim.x + threadIdx.x) >> 5;
    int lane = threadIdx.x & 31;
    if (gw >= NB * CDIM) return;
    int n = gw / CDIM;
    int c = gw - n * CDIM;

    float wj0 = w_jeff[lane * 2 + 0];
    float wj1 = w_jeff[lane * 2 + 1];
    float wcc = w_cc[lane];
    float d0  = 1.0f - sigmoid_acc(w_sf0[0]);
    float d1  = 1.0f - sigmoid_acc(w_sf1[0]);
    const float invlif = 1.0f / 1.5f;
    const size_t P0 = (size_t)BATCH * CDIM;

    float yf0 = 0.f, yf1 = 0.f;
    float v = 0.f, g = 0.f, vI = 0.f, fo = 0.f;

    const float* xb = x + (size_t)n * 2 * CDIM + c;
#pragma unroll
    for (int t = 0; t < T_STEPS; t++) {
        float x0 = xb[(size_t)t * NB * 2 * CDIM];
        float x1 = xb[(size_t)t * NB * 2 * CDIM + CDIM];
        yf0 = 0.5f * yf0 + x0;
        yf1 = 0.5f * yf1 + x1;
        float u = wj0 * yf0 + wj1 * yf1;
        v = v + (u - v) * invlif;
        float s = (v >= 1.0f) ? 1.0f : 0.0f;
        v = (v >= 1.0f) ? 0.0f : v;
        g = d0 * g + s;
        float r = g * wcc;
#pragma unroll
        for (int off = 16; off; off >>= 1)
            r += __shfl_xor_sync(0xffffffffu, r, off);
        vI += r;
        float s1 = (vI >= 1.0f) ? 1.0f : 0.0f;
        vI = (vI >= 1.0f) ? 0.0f : vI;
        fo = d1 * fo + s1;
        __nv_bfloat16 hh, mm, ll;
        split3(fo, hh, mm, ll);
        size_t id = ((size_t)t * NB + n) * CDIM + c;
        if (lane == 0)      g_A1s[id]          = hh;
        else if (lane == 1) g_A1s[P0 + id]     = mm;
        else if (lane == 2) g_A1s[2 * P0 + id] = ll;
        else if (lane == 3) g_F1[id]           = fo;
    }
}

// ---------------------------------------------------------------------------
// 9-pair split-bf16 tensor GEMM (R6, numerically verified as provisional):
// U[m][o] = sum_{i,j} As[i][m][k] * Ws[j][o][k]
// ---------------------------------------------------------------------------
#define PAD_B      144
#define TILE_B     (128 * PAD_B)
#define STAGE_B    (6 * TILE_B)
#define SMEM9      (2 * STAGE_B)      // 221184

static __device__ __forceinline__ uint32_t smem_u32(const void* p) {
    return (uint32_t)__cvta_generic_to_shared(p);
}
static __device__ __forceinline__ void cp16(uint32_t dst, const void* src) {
    asm volatile("cp.async.cg.shared.global [%0], [%1], 16;"
                 :: "r"(dst), "l"(src) : "memory");
}
static __device__ __forceinline__ uint32_t ld32(const char* p) {
    return *reinterpret_cast<const uint32_t*>(p);
}
static __device__ __forceinline__ void mma16816(float* c, const uint32_t* a,
                                                const uint32_t* b) {
    asm volatile(
        "mma.sync.aligned.m16n8k16.row.col.f32.bf16.bf16.f32 "
        "{%0,%1,%2,%3}, {%4,%5,%6,%7}, {%8,%9}, {%0,%1,%2,%3};"
        : "+f"(c[0]), "+f"(c[1]), "+f"(c[2]), "+f"(c[3])
        : "r"(a[0]), "r"(a[1]), "r"(a[2]), "r"(a[3]), "r"(b[0]), "r"(b[1]));
}

__global__ void __launch_bounds__(256, 1)
gemm9_kernel(const __nv_bfloat16* __restrict__ Ws,
             const __nv_bfloat16* __restrict__ As,
             float* __restrict__ U, int N, int K)
{
    extern __shared__ __align__(16) char smem[];
    uint32_t sb = smem_u32(smem);

    int tid  = threadIdx.x;
    int wid  = tid >> 5;
    int lane = tid & 31;
    int wm   = wid & 1;
    int wn   = wid >> 1;
    int m0 = blockIdx.y * 128;
    int n0 = blockIdx.x * 128;
    int NC = K / 64;
    size_t NK = (size_t)N * K;
    size_t MK = (size_t)BATCH * K;

    float acc[4][4][4];
#pragma unroll
    for (int i = 0; i < 4; i++)
#pragma unroll
        for (int j = 0; j < 4; j++)
#pragma unroll
            for (int q2 = 0; q2 < 4; q2++) acc[i][j][q2] = 0.f;

    int lrow = tid >> 3;
    int lc16 = tid & 7;

    auto issue_load = [&](int c, int b) {
        int kk = c * 64;
        uint32_t base = sb + b * STAGE_B;
#pragma unroll
        for (int sp = 0; sp < 3; sp++) {
            const __nv_bfloat16* Ag = As + sp * MK + (size_t)m0 * K + kk;
            const __nv_bfloat16* Bg = Ws + sp * NK + (size_t)n0 * K + kk;
            uint32_t At = base + sp * TILE_B;
            uint32_t Bt = base + (3 + sp) * TILE_B;
#pragma unroll
            for (int p = 0; p < 4; p++) {
                int row = lrow + p * 32;
                uint32_t off = (uint32_t)row * PAD_B + lc16 * 16;
                cp16(At + off, Ag + (size_t)row * K + lc16 * 8);
                cp16(Bt + off, Bg + (size_t)row * K + lc16 * 8);
            }
        }
        asm volatile("cp.async.commit_group;" ::: "memory");
    };

    issue_load(0, 0);

    int g = lane >> 2;
    int q = lane & 3;

    for (int c = 0; c < NC; c++) {
        int buf = c & 1;
        if (c + 1 < NC) {
            issue_load(c + 1, buf ^ 1);
            asm volatile("cp.async.wait_group 1;" ::: "memory");
        } else {
            asm volatile("cp.async.wait_group 0;" ::: "memory");
        }
        __syncthreads();

        const char* Sb = smem + buf * STAGE_B;
#pragma unroll
        for (int ks = 0; ks < 4; ks++) {
            int kbyte = ks * 32 + q * 4;
#pragma unroll
            for (int spA = 2; spA >= 0; spA--) {
                uint32_t a[4][4];
                const char* At = Sb + spA * TILE_B;
#pragma unroll
                for (int mi = 0; mi < 4; mi++) {
                    const char* base = At + (size_t)(wm * 64 + mi * 16 + g) * PAD_B + kbyte;
                    a[mi][0] = ld32(base);
                    a[mi][1] = ld32(base + 8 * PAD_B);
                    a[mi][2] = ld32(base + 16);
                    a[mi][3] = ld32(base + 8 * PAD_B + 16);
                }
#pragma unroll
                for (int spB = 2; spB >= 0; spB--) {
                    const char* Bt = Sb + (3 + spB) * TILE_B;
#pragma unroll
                    for (int ni = 0; ni < 4; ni++) {
                        uint32_t b[2];
                        const char* base = Bt + (size_t)(wn * 32 + ni * 8 + g) * PAD_B + kbyte;
                        b[0] = ld32(base);
                        b[1] = ld32(base + 16);
#pragma unroll
                        for (int mi = 0; mi < 4; mi++)
                            mma16816(acc[mi][ni], a[mi], b);
                    }
                }
            }
        }
        __syncthreads();
    }

    int erow = m0 + wm * 64 + g;
    int ecol = n0 + wn * 32 + q * 2;
#pragma unroll
    for (int mi = 0; mi < 4; mi++) {
#pragma unroll
        for (int ni = 0; ni < 4; ni++) {
            float* p0 = U + (size_t)(erow + mi * 16) * N + ecol + ni * 8;
            float* p1 = U + (size_t)(erow + mi * 16 + 8) * N + ecol + ni * 8;
            *reinterpret_cast<float2*>(p0) = make_float2(acc[mi][ni][0], acc[mi][ni][1]);
            *reinterpret_cast<float2*>(p1) = make_float2(acc[mi][ni][2], acc[mi][ni][3]);
        }
    }
}

// ---------------------------------------------------------------------------
// Flag + provisional IF + trace (mid layers): writes next trace (splits+fp32),
// flags neurons whose any-step margin < MARGIN into per-n list.
// ---------------------------------------------------------------------------
__global__ void flag_mid(const float* __restrict__ U,
                         __nv_bfloat16* __restrict__ Fs, float* __restrict__ Ffp,
                         const float* __restrict__ w_sf, int Odim,
                         int* __restrict__ cnt, int* __restrict__ lst)
{
    int idx = blockIdx.x * blockDim.x + threadIdx.x;
    if (idx >= NB * Odim) return;
    int o = idx % Odim;
    int n = idx / Odim;
    float d = 1.0f - sigmoid_acc(w_sf[0]);
    size_t P = (size_t)BATCH * Odim;
    float v = 0.f, f = 0.f;
    int flg = 0;
#pragma unroll
    for (int t = 0; t < T_STEPS; t++) {
        size_t id = ((size_t)t * NB + n) * Odim + o;
        v += U[id];
        if (fabsf(v - 1.0f) < MARGIN) flg = 1;
        float s = (v >= 1.0f) ? 1.0f : 0.0f;
        v = (v >= 1.0f) ? 0.0f : v;
        f = d * f + s;
        __nv_bfloat16 hh, mm, ll;
        split3(f, hh, mm, ll);
        Fs[id] = hh; Fs[P + id] = mm; Fs[2 * P + id] = ll;
        Ffp[id] = f;
    }
    if (flg) {
        int slot = atomicAdd(&cnt[n], 1);
        lst[n * Odim + slot] = o;
    }
}

// Last layer: flag only (no trace)
__global__ void flag_last(const float* __restrict__ U, int Odim,
                          int* __restrict__ cnt, int* __restrict__ lst)
{
    int idx = blockIdx.x * blockDim.x + threadIdx.x;
    if (idx >= NB * Odim) return;
    int o = idx % Odim;
    int n = idx / Odim;
    float v = 0.f;
    int flg = 0;
#pragma unroll
    for (int t = 0; t < T_STEPS; t++) {
        v += U[((size_t)t * NB + n) * Odim + o];
        if (fabsf(v - 1.0f) < MARGIN) flg = 1;
        v = (v >= 1.0f) ? 0.0f : v;
    }
    if (flg) {
        int slot = atomicAdd(&cnt[n], 1);
        lst[n * Odim + slot] = o;
    }
}

// ---------------------------------------------------------------------------
// Exact recompute for flagged neurons (sequential-k fp32 chain == R1 GEMM).
// One thread per flagged (n,o); F[t][n][:] staged through SMEM per n-block.
// ---------------------------------------------------------------------------
#define KC 128

__global__ void __launch_bounds__(256)
recompute_mid(const float* __restrict__ W, const float* __restrict__ Fin,
              const int* __restrict__ cnt, const int* __restrict__ lst,
              __nv_bfloat16* __restrict__ Fs, float* __restrict__ Ffp,
              const float* __restrict__ w_sf, int Kdim, int Odim)
{
    __shared__ float sF[T_STEPS * KC];
    int n = blockIdx.x;
    int tid = threadIdx.x;
    int c = cnt[n];
    int base = blockIdx.y * 256;
    if (base >= c) return;
    int o = (base + tid < c) ? lst[n * Odim + base + tid] : -1;

    float hacc[T_STEPS];
#pragma unroll
    for (int t = 0; t < T_STEPS; t++) hacc[t] = 0.f;

    for (int k0 = 0; k0 < Kdim; k0 += KC) {
        __syncthreads();
        for (int i = tid; i < T_STEPS * KC; i += 256) {
            int t = i >> 7, kk = i & (KC - 1);
            sF[i] = Fin[((size_t)t * NB + n) * Kdim + k0 + kk];
        }
        __syncthreads();
        if (o >= 0) {
            const float* wr = W + (size_t)o * Kdim + k0;
            for (int kb = 0; kb < KC; kb += 16) {
                float4 w0 = *(const float4*)(wr + kb);
                float4 w1 = *(const float4*)(wr + kb + 4);
                float4 w2 = *(const float4*)(wr + kb + 8);
                float4 w3 = *(const float4*)(wr + kb + 12);
                float wv[16] = {w0.x, w0.y, w0.z, w0.w, w1.x, w1.y, w1.z, w1.w,
                                w2.x, w2.y, w2.z, w2.w, w3.x, w3.y, w3.z, w3.w};
#pragma unroll
                for (int kk = 0; kk < 16; kk++)
#pragma unroll
                    for (int t = 0; t < T_STEPS; t++)
                        hacc[t] = fmaf(wv[kk], sF[t * KC + kb + kk], hacc[t]);
            }
        }
    }

    if (o >= 0) {
        float d = 1.0f - sigmoid_acc(w_sf[0]);
        size_t P = (size_t)BATCH * Odim;
        float v = 0.f, f = 0.f;
#pragma unroll
        for (int t = 0; t < T_STEPS; t++) {
            v += hacc[t];
            float s = (v >= 1.0f) ? 1.0f : 0.0f;
            v = (v >= 1.0f) ? 0.0f : v;
            f = d * f + s;
            __nv_bfloat16 hh, mm, ll;
            split3(f, hh, mm, ll);
            size_t id = ((size_t)t * NB + n) * Odim + o;
            Fs[id] = hh; Fs[P + id] = mm; Fs[2 * P + id] = ll;
            Ffp[id] = f;
        }
    }
}

__global__ void __launch_bounds__(256)
recompute_last(const float* __restrict__ W, const float* __restrict__ Fin,
               const int* __restrict__ cnt, const int* __restrict__ lst,
               float* __restrict__ U, int Kdim, int Odim)
{
    __shared__ float sF[T_STEPS * KC];
    int n = blockIdx.x;
    int tid = threadIdx.x;
    int c = cnt[n];
    int base = blockIdx.y * 256;
    if (base >= c) return;
    int o = (base + tid < c) ? lst[n * Odim + base + tid] : -1;

    float hacc[T_STEPS];
#pragma unroll
    for (int t = 0; t < T_STEPS; t++) hacc[t] = 0.f;

    for (int k0 = 0; k0 < Kdim; k0 += KC) {
        __syncthreads();
        for (int i = tid; i < T_STEPS * KC; i += 256) {
            int t = i >> 7, kk = i & (KC - 1);
            sF[i] = Fin[((size_t)t * NB + n) * Kdim + k0 + kk];
        }
        __syncthreads();
        if (o >= 0) {
            const float* wr = W + (size_t)o * Kdim + k0;
            for (int kb = 0; kb < KC; kb += 16) {
                float4 w0 = *(const float4*)(wr + kb);
                float4 w1 = *(const float4*)(wr + kb + 4);
                float4 w2 = *(const float4*)(wr + kb + 8);
                float4 w3 = *(const float4*)(wr + kb + 12);
                float wv[16] = {w0.x, w0.y, w0.z, w0.w, w1.x, w1.y, w1.z, w1.w,
                                w2.x, w2.y, w2.z, w2.w, w3.x, w3.y, w3.z, w3.w};
#pragma unroll
                for (int kk = 0; kk < 16; kk++)
#pragma unroll
                    for (int t = 0; t < T_STEPS; t++)
                        hacc[t] = fmaf(wv[kk], sF[t * KC + kb + kk], hacc[t]);
            }
        }
    }

    if (o >= 0) {
#pragma unroll
        for (int t = 0; t < T_STEPS; t++)
            U[((size_t)t * NB + n) * Odim + o] = hacc[t];
    }
}

// ---------------------------------------------------------------------------
// Final: IF over U3, dot W_out, + b_out, cumsum (verbatim R1).
// ---------------------------------------------------------------------------
__global__ void final_kernel(const float* __restrict__ Wout,
                             const float* __restrict__ bout,
                             float* __restrict__ out)
{
    int n = blockIdx.x;
    int f = threadIdx.x;
    __shared__ float red[16];
    float v   = 0.f;
    float wf  = Wout[f];
    float acc = 0.f;
    float b   = bout[0];
    int lane = f & 31, wid = f >> 5;
    for (int t = 0; t < T_STEPS; t++) {
        v += g_U3[((size_t)t * NB + n) * F3DIM + f];
        float s = (v >= 1.0f) ? 1.0f : 0.0f;
        v = (v >= 1.0f) ? 0.0f : v;
        float p = wf * s;
#pragma unroll
        for (int off = 16; off; off >>= 1)
            p += __shfl_xor_sync(0xffffffffu, p, off);
        if (lane == 0) red[wid] = p;
        __syncthreads();
        if (f < 16) {
            float q = red[f];
#pragma unroll
            for (int off = 8; off; off >>= 1)
                q += __shfl_xor_sync(0x0000ffffu, q, off);
            if (f == 0) {
                acc += q + b;
                out[t * NB + n] = acc;
            }
        }
        __syncthreads();
    }
}

// ---------------------------------------------------------------------------
extern "C" void kernel_launch(void* const* d_in, const int* in_sizes, int n_in,
                              void* d_out, int out_size)
{
    (void)in_sizes; (void)n_in; (void)out_size;
    const float* x     = (const float*)d_in[0];
    const float* wjeff = (const float*)d_in[1];
    const float* wcc   = (const float*)d_in[2];
    const float* wsf0  = (const float*)d_in[3];
    const float* W1    = (const float*)d_in[4];
    const float* wsf1  = (const float*)d_in[5];
    const float* W2    = (const float*)d_in[6];
    const float* wsf2  = (const float*)d_in[7];
    const float* W3    = (const float*)d_in[8];
    const float* wsf3  = (const float*)d_in[9];
    const float* Wout  = (const float*)d_in[10];
    const float* bout  = (const float*)d_in[11];
    float* out = (float*)d_out;

    __nv_bfloat16 *A1, *A2, *A3, *W1s, *W2s, *W3s;
    float *F1, *F2, *F3, *U1, *U2, *U3;
    int *c1, *c2, *c3, *l1, *l2, *l3;
    cudaGetSymbolAddress((void**)&A1, g_A1s);
    cudaGetSymbolAddress((void**)&A2, g_A2s);
    cudaGetSymbolAddress((void**)&A3, g_A3s);
    cudaGetSymbolAddress((void**)&F1, g_F1);
    cudaGetSymbolAddress((void**)&F2, g_F2);
    cudaGetSymbolAddress((void**)&F3, g_F3);
    cudaGetSymbolAddress((void**)&U1, g_U1);
    cudaGetSymbolAddress((void**)&U2, g_U2);
    cudaGetSymbolAddress((void**)&U3, g_U3);
    cudaGetSymbolAddress((void**)&W1s, g_W1s);
    cudaGetSymbolAddress((void**)&W2s, g_W2s);
    cudaGetSymbolAddress((void**)&W3s, g_W3s);
    cudaGetSymbolAddress((void**)&c1, g_cnt1);
    cudaGetSymbolAddress((void**)&c2, g_cnt2);
    cudaGetSymbolAddress((void**)&c3, g_cnt3);
    cudaGetSymbolAddress((void**)&l1, g_lst1);
    cudaGetSymbolAddress((void**)&l2, g_lst2);
    cudaGetSymbolAddress((void**)&l3, g_lst3);

    cudaFuncSetAttribute(gemm9_kernel,
                         cudaFuncAttributeMaxDynamicSharedMemorySize, SMEM9);

    zero_counts<<<1, NB>>>();

    split_kernel<<<(F1DIM * CDIM + 255) / 256, 256>>>(W1, W1s, F1DIM * CDIM);
    split_kernel<<<(F2DIM * F1DIM + 255) / 256, 256>>>(W2, W2s, F2DIM * F1DIM);
    split_kernel<<<(F3DIM * F2DIM + 255) / 256, 256>>>(W3, W3s, F3DIM * F2DIM);

    stage1_kernel<<<(NB * CDIM * 32) / 256, 256>>>(x, wjeff, wcc, wsf0, wsf1);

    // Layer 1
    gemm9_kernel<<<dim3(F1DIM / 128, BATCH / 128), 256, SMEM9>>>(W1s, A1, U1, F1DIM, CDIM);
    flag_mid<<<(NB * F1DIM + 255) / 256, 256>>>(U1, A2, F2, wsf2, F1DIM, c1, l1);
    recompute_mid<<<dim3(NB, F1DIM / 256), 256>>>(W1, F1, c1, l1, A2, F2, wsf2, CDIM, F1DIM);

    // Layer 2
    gemm9_kernel<<<dim3(F2DIM / 128, BATCH / 128), 256, SMEM9>>>(W2s, A2, U2, F2DIM, F1DIM);
    flag_mid<<<(NB * F2DIM + 255) / 256, 256>>>(U2, A3, F3, wsf3, F2DIM, c2, l2);
    recompute_mid<<<dim3(NB, F2DIM / 256), 256>>>(W2, F2, c2, l2, A3, F3, wsf3, F1DIM, F2DIM);

    // Layer 3
    gemm9_kernel<<<dim3(F3DIM / 128, BATCH / 128), 256, SMEM9>>>(W3s, A3, U3, F3DIM, F2DIM);
    flag_last<<<(NB * F3DIM + 255) / 256, 256>>>(U3, F3DIM, c3, l3);
    recompute_last<<<dim3(NB, F3DIM / 256), 256>>>(W3, F3, c3, l3, U3, F2DIM, F3DIM);

    final_kernel<<<NB, F3DIM>>>(Wout, bout, out);
}

// round 15
// speedup vs baseline: 1.4405x; 1.4405x over previous
#include <cuda_runtime.h>
#include <cuda_bf16.h>
#include <math.h>
#include <stdint.h>

#define T_STEPS 32
#define NB      64
#define CDIM    512
#define F1DIM   2048
#define F2DIM   1024
#define F3DIM   512
#define BATCH   (T_STEPS * NB)   // 2048

#define MARGIN 4e-3f             // certified decision margin

// ---------------- scratch (device globals; no allocation allowed) -------------
// trace split planes [2][BATCH][K] + fp32 exact traces
__device__ __align__(16) __nv_bfloat16 g_A1s[2 * BATCH * CDIM];
__device__ __align__(16) __nv_bfloat16 g_A2s[2 * BATCH * F1DIM];
__device__ __align__(16) __nv_bfloat16 g_A3s[2 * BATCH * F2DIM];
__device__ __align__(16) float g_F1[BATCH * CDIM];
__device__ __align__(16) float g_F2[BATCH * F1DIM];
__device__ __align__(16) float g_F3[BATCH * F2DIM];
__device__ __align__(16) float g_U1[BATCH * F1DIM];
__device__ __align__(16) float g_U2[BATCH * F2DIM];
__device__ __align__(16) float g_U3[BATCH * F3DIM];
// weight split planes [2][O][K]
__device__ __align__(16) __nv_bfloat16 g_W1s[2 * F1DIM * CDIM];
__device__ __align__(16) __nv_bfloat16 g_W2s[2 * F2DIM * F1DIM];
__device__ __align__(16) __nv_bfloat16 g_W3s[2 * F3DIM * F2DIM];
// flag lists
__device__ int g_cnt1[NB], g_cnt2[NB], g_cnt3[NB];
__device__ int g_lst1[NB * F1DIM], g_lst2[NB * F2DIM], g_lst3[NB * F3DIM];

__device__ __forceinline__ float sigmoid_acc(float w) {
    return 1.0f / (1.0f + expf(-w));
}
__device__ __forceinline__ void split2(float w, __nv_bfloat16& h, __nv_bfloat16& m) {
    h = __float2bfloat16(w);
    float r1 = w - __bfloat162float(h);
    m = __float2bfloat16(r1);
}

__global__ void zero_counts() {
    int i = threadIdx.x;
    if (i < NB) { g_cnt1[i] = 0; g_cnt2[i] = 0; g_cnt3[i] = 0; }
}

// ---------------------------------------------------------------------------
__global__ void split_kernel(const float* __restrict__ W,
                             __nv_bfloat16* __restrict__ dst, int n)
{
    int i = blockIdx.x * blockDim.x + threadIdx.x;
    if (i >= n) return;
    __nv_bfloat16 h, m;
    split2(W[i], h, m);
    dst[i] = h; dst[n + i] = m;
}

// ---------------------------------------------------------------------------
// Stage 1 (R1-exact math) -> trace f1 fp32 + 2 split planes
// ---------------------------------------------------------------------------
__global__ void stage1_kernel(const float* __restrict__ x,
                              const float* __restrict__ w_jeff,
                              const float* __restrict__ w_cc,
                              const float* __restrict__ w_sf0,
                              const float* __restrict__ w_sf1)
{
    int gw   = (blockIdx.x * blockDim.x + threadIdx.x) >> 5;
    int lane = threadIdx.x & 31;
    if (gw >= NB * CDIM) return;
    int n = gw / CDIM;
    int c = gw - n * CDIM;

    float wj0 = w_jeff[lane * 2 + 0];
    float wj1 = w_jeff[lane * 2 + 1];
    float wcc = w_cc[lane];
    float d0  = 1.0f - sigmoid_acc(w_sf0[0]);
    float d1  = 1.0f - sigmoid_acc(w_sf1[0]);
    const float invlif = 1.0f / 1.5f;
    const size_t P0 = (size_t)BATCH * CDIM;

    float yf0 = 0.f, yf1 = 0.f;
    float v = 0.f, g = 0.f, vI = 0.f, fo = 0.f;

    const float* xb = x + (size_t)n * 2 * CDIM + c;
#pragma unroll
    for (int t = 0; t < T_STEPS; t++) {
        float x0 = xb[(size_t)t * NB * 2 * CDIM];
        float x1 = xb[(size_t)t * NB * 2 * CDIM + CDIM];
        yf0 = 0.5f * yf0 + x0;
        yf1 = 0.5f * yf1 + x1;
        float u = wj0 * yf0 + wj1 * yf1;
        v = v + (u - v) * invlif;
        float s = (v >= 1.0f) ? 1.0f : 0.0f;
        v = (v >= 1.0f) ? 0.0f : v;
        g = d0 * g + s;
        float r = g * wcc;
#pragma unroll
        for (int off = 16; off; off >>= 1)
            r += __shfl_xor_sync(0xffffffffu, r, off);
        vI += r;
        float s1 = (vI >= 1.0f) ? 1.0f : 0.0f;
        vI = (vI >= 1.0f) ? 0.0f : vI;
        fo = d1 * fo + s1;
        __nv_bfloat16 hh, mm;
        split2(fo, hh, mm);
        size_t id = ((size_t)t * NB + n) * CDIM + c;
        if (lane == 0)      g_A1s[id]      = hh;
        else if (lane == 1) g_A1s[P0 + id] = mm;
        else if (lane == 2) g_F1[id]       = fo;
    }
}

// ---------------------------------------------------------------------------
// 3-pair split-bf16 tensor GEMM (provisional; deviation ~7e-5 << MARGIN):
// U[m][o] ~= (A0+A1)(W0+W1) with pairs A0W0 + A0W1 + A1W0
// ---------------------------------------------------------------------------
#define PAD_B      144
#define TILE_B     (128 * PAD_B)
#define STAGE_B    (4 * TILE_B)       // A0,A1,B0,B1
#define SMEM3      (2 * STAGE_B)      // 147456

static __device__ __forceinline__ uint32_t smem_u32(const void* p) {
    return (uint32_t)__cvta_generic_to_shared(p);
}
static __device__ __forceinline__ void cp16(uint32_t dst, const void* src) {
    asm volatile("cp.async.cg.shared.global [%0], [%1], 16;"
                 :: "r"(dst), "l"(src) : "memory");
}
static __device__ __forceinline__ uint32_t ld32(const char* p) {
    return *reinterpret_cast<const uint32_t*>(p);
}
static __device__ __forceinline__ void mma16816(float* c, const uint32_t* a,
                                                const uint32_t* b) {
    asm volatile(
        "mma.sync.aligned.m16n8k16.row.col.f32.bf16.bf16.f32 "
        "{%0,%1,%2,%3}, {%4,%5,%6,%7}, {%8,%9}, {%0,%1,%2,%3};"
        : "+f"(c[0]), "+f"(c[1]), "+f"(c[2]), "+f"(c[3])
        : "r"(a[0]), "r"(a[1]), "r"(a[2]), "r"(a[3]), "r"(b[0]), "r"(b[1]));
}

__global__ void __launch_bounds__(256, 1)
gemm3_kernel(const __nv_bfloat16* __restrict__ Ws,
             const __nv_bfloat16* __restrict__ As,
             float* __restrict__ U, int N, int K)
{
    extern __shared__ __align__(16) char smem[];
    uint32_t sb = smem_u32(smem);

    int tid  = threadIdx.x;
    int wid  = tid >> 5;
    int lane = tid & 31;
    int wm   = wid & 1;
    int wn   = wid >> 1;
    int m0 = blockIdx.y * 128;
    int n0 = blockIdx.x * 128;
    int NC = K / 64;
    size_t NK = (size_t)N * K;
    size_t MK = (size_t)BATCH * K;

    float acc[4][4][4];
#pragma unroll
    for (int i = 0; i < 4; i++)
#pragma unroll
        for (int j = 0; j < 4; j++)
#pragma unroll
            for (int q2 = 0; q2 < 4; q2++) acc[i][j][q2] = 0.f;

    int lrow = tid >> 3;
    int lc16 = tid & 7;

    auto issue_load = [&](int c, int b) {
        int kk = c * 64;
        uint32_t base = sb + b * STAGE_B;
#pragma unroll
        for (int sp = 0; sp < 2; sp++) {
            const __nv_bfloat16* Ag = As + sp * MK + (size_t)m0 * K + kk;
            const __nv_bfloat16* Bg = Ws + sp * NK + (size_t)n0 * K + kk;
            uint32_t At = base + sp * TILE_B;
            uint32_t Bt = base + (2 + sp) * TILE_B;
#pragma unroll
            for (int p = 0; p < 4; p++) {
                int row = lrow + p * 32;
                uint32_t off = (uint32_t)row * PAD_B + lc16 * 16;
                cp16(At + off, Ag + (size_t)row * K + lc16 * 8);
                cp16(Bt + off, Bg + (size_t)row * K + lc16 * 8);
            }
        }
        asm volatile("cp.async.commit_group;" ::: "memory");
    };

    issue_load(0, 0);

    int g = lane >> 2;
    int q = lane & 3;

    for (int c = 0; c < NC; c++) {
        int buf = c & 1;
        if (c + 1 < NC) {
            issue_load(c + 1, buf ^ 1);
            asm volatile("cp.async.wait_group 1;" ::: "memory");
        } else {
            asm volatile("cp.async.wait_group 0;" ::: "memory");
        }
        __syncthreads();

        const char* Sb = smem + buf * STAGE_B;
#pragma unroll
        for (int ks = 0; ks < 4; ks++) {
            int kbyte = ks * 32 + q * 4;
            // load A fragments, both planes
            uint32_t a[2][4][4];
#pragma unroll
            for (int sp = 0; sp < 2; sp++) {
                const char* At = Sb + sp * TILE_B;
#pragma unroll
                for (int mi = 0; mi < 4; mi++) {
                    const char* base = At + (size_t)(wm * 64 + mi * 16 + g) * PAD_B + kbyte;
                    a[sp][mi][0] = ld32(base);
                    a[sp][mi][1] = ld32(base + 8 * PAD_B);
                    a[sp][mi][2] = ld32(base + 16);
                    a[sp][mi][3] = ld32(base + 8 * PAD_B + 16);
                }
            }
            // B plane 0: pairs (A1,B0), (A0,B0)
            {
                const char* Bt = Sb + 2 * TILE_B;
#pragma unroll
                for (int ni = 0; ni < 4; ni++) {
                    uint32_t b[2];
                    const char* base = Bt + (size_t)(wn * 32 + ni * 8 + g) * PAD_B + kbyte;
                    b[0] = ld32(base);
                    b[1] = ld32(base + 16);
#pragma unroll
                    for (int mi = 0; mi < 4; mi++) {
                        mma16816(acc[mi][ni], a[1][mi], b);
                        mma16816(acc[mi][ni], a[0][mi], b);
                    }
                }
            }
            // B plane 1: pair (A0,B1)
            {
                const char* Bt = Sb + 3 * TILE_B;
#pragma unroll
                for (int ni = 0; ni < 4; ni++) {
                    uint32_t b[2];
                    const char* base = Bt + (size_t)(wn * 32 + ni * 8 + g) * PAD_B + kbyte;
                    b[0] = ld32(base);
                    b[1] = ld32(base + 16);
#pragma unroll
                    for (int mi = 0; mi < 4; mi++)
                        mma16816(acc[mi][ni], a[0][mi], b);
                }
            }
        }
        __syncthreads();
    }

    int erow = m0 + wm * 64 + g;
    int ecol = n0 + wn * 32 + q * 2;
#pragma unroll
    for (int mi = 0; mi < 4; mi++) {
#pragma unroll
        for (int ni = 0; ni < 4; ni++) {
            float* p0 = U + (size_t)(erow + mi * 16) * N + ecol + ni * 8;
            float* p1 = U + (size_t)(erow + mi * 16 + 8) * N + ecol + ni * 8;
            *reinterpret_cast<float2*>(p0) = make_float2(acc[mi][ni][0], acc[mi][ni][1]);
            *reinterpret_cast<float2*>(p1) = make_float2(acc[mi][ni][2], acc[mi][ni][3]);
        }
    }
}

// ---------------------------------------------------------------------------
// Flag + provisional IF + trace (mid layers): writes next trace (2 planes+fp32),
// flags neurons whose any-step margin < MARGIN into per-n list.
// ---------------------------------------------------------------------------
__global__ void flag_mid(const float* __restrict__ U,
                         __nv_bfloat16* __restrict__ Fs, float* __restrict__ Ffp,
                         const float* __restrict__ w_sf, int Odim,
                         int* __restrict__ cnt, int* __restrict__ lst)
{
    int idx = blockIdx.x * blockDim.x + threadIdx.x;
    if (idx >= NB * Odim) return;
    int o = idx % Odim;
    int n = idx / Odim;
    float d = 1.0f - sigmoid_acc(w_sf[0]);
    size_t P = (size_t)BATCH * Odim;
    float v = 0.f, f = 0.f;
    int flg = 0;
#pragma unroll
    for (int t = 0; t < T_STEPS; t++) {
        size_t id = ((size_t)t * NB + n) * Odim + o;
        v += U[id];
        if (fabsf(v - 1.0f) < MARGIN) flg = 1;
        float s = (v >= 1.0f) ? 1.0f : 0.0f;
        v = (v >= 1.0f) ? 0.0f : v;
        f = d * f + s;
        __nv_bfloat16 hh, mm;
        split2(f, hh, mm);
        Fs[id] = hh; Fs[P + id] = mm;
        Ffp[id] = f;
    }
    if (flg) {
        int slot = atomicAdd(&cnt[n], 1);
        lst[n * Odim + slot] = o;
    }
}

// Last layer: flag only
__global__ void flag_last(const float* __restrict__ U, int Odim,
                          int* __restrict__ cnt, int* __restrict__ lst)
{
    int idx = blockIdx.x * blockDim.x + threadIdx.x;
    if (idx >= NB * Odim) return;
    int o = idx % Odim;
    int n = idx / Odim;
    float v = 0.f;
    int flg = 0;
#pragma unroll
    for (int t = 0; t < T_STEPS; t++) {
        v += U[((size_t)t * NB + n) * Odim + o];
        if (fabsf(v - 1.0f) < MARGIN) flg = 1;
        v = (v >= 1.0f) ? 0.0f : v;
    }
    if (flg) {
        int slot = atomicAdd(&cnt[n], 1);
        lst[n * Odim + slot] = o;
    }
}

// ---------------------------------------------------------------------------
// Exact recompute for flagged neurons (sequential-k fp32 chain == R1 GEMM).
// ---------------------------------------------------------------------------
#define KC 128

__global__ void __launch_bounds__(256)
recompute_mid(const float* __restrict__ W, const float* __restrict__ Fin,
              const int* __restrict__ cnt, const int* __restrict__ lst,
              __nv_bfloat16* __restrict__ Fs, float* __restrict__ Ffp,
              const float* __restrict__ w_sf, int Kdim, int Odim)
{
    __shared__ float sF[T_STEPS * KC];
    int n = blockIdx.x;
    int tid = threadIdx.x;
    int c = cnt[n];
    int base = blockIdx.y * 256;
    if (base >= c) return;
    int o = (base + tid < c) ? lst[n * Odim + base + tid] : -1;

    float hacc[T_STEPS];
#pragma unroll
    for (int t = 0; t < T_STEPS; t++) hacc[t] = 0.f;

    for (int k0 = 0; k0 < Kdim; k0 += KC) {
        __syncthreads();
        for (int i = tid; i < T_STEPS * KC; i += 256) {
            int t = i >> 7, kk = i & (KC - 1);
            sF[i] = Fin[((size_t)t * NB + n) * Kdim + k0 + kk];
        }
        __syncthreads();
        if (o >= 0) {
            const float* wr = W + (size_t)o * Kdim + k0;
            for (int kb = 0; kb < KC; kb += 16) {
                float4 w0 = *(const float4*)(wr + kb);
                float4 w1 = *(const float4*)(wr + kb + 4);
                float4 w2 = *(const float4*)(wr + kb + 8);
                float4 w3 = *(const float4*)(wr + kb + 12);
                float wv[16] = {w0.x, w0.y, w0.z, w0.w, w1.x, w1.y, w1.z, w1.w,
                                w2.x, w2.y, w2.z, w2.w, w3.x, w3.y, w3.z, w3.w};
#pragma unroll
                for (int kk = 0; kk < 16; kk++)
#pragma unroll
                    for (int t = 0; t < T_STEPS; t++)
                        hacc[t] = fmaf(wv[kk], sF[t * KC + kb + kk], hacc[t]);
            }
        }
    }

    if (o >= 0) {
        float d = 1.0f - sigmoid_acc(w_sf[0]);
        size_t P = (size_t)BATCH * Odim;
        float v = 0.f, f = 0.f;
#pragma unroll
        for (int t = 0; t < T_STEPS; t++) {
            v += hacc[t];
            float s = (v >= 1.0f) ? 1.0f : 0.0f;
            v = (v >= 1.0f) ? 0.0f : v;
            f = d * f + s;
            __nv_bfloat16 hh, mm;
            split2(f, hh, mm);
            size_t id = ((size_t)t * NB + n) * Odim + o;
            Fs[id] = hh; Fs[P + id] = mm;
            Ffp[id] = f;
        }
    }
}

__global__ void __launch_bounds__(256)
recompute_last(const float* __restrict__ W, const float* __restrict__ Fin,
               const int* __restrict__ cnt, const int* __restrict__ lst,
               float* __restrict__ U, int Kdim, int Odim)
{
    __shared__ float sF[T_STEPS * KC];
    int n = blockIdx.x;
    int tid = threadIdx.x;
    int c = cnt[n];
    int base = blockIdx.y * 256;
    if (base >= c) return;
    int o = (base + tid < c) ? lst[n * Odim + base + tid] : -1;

    float hacc[T_STEPS];
#pragma unroll
    for (int t = 0; t < T_STEPS; t++) hacc[t] = 0.f;

    for (int k0 = 0; k0 < Kdim; k0 += KC) {
        __syncthreads();
        for (int i = tid; i < T_STEPS * KC; i += 256) {
            int t = i >> 7, kk = i & (KC - 1);
            sF[i] = Fin[((size_t)t * NB + n) * Kdim + k0 + kk];
        }
        __syncthreads();
        if (o >= 0) {
            const float* wr = W + (size_t)o * Kdim + k0;
            for (int kb = 0; kb < KC; kb += 16) {
                float4 w0 = *(const float4*)(wr + kb);
                float4 w1 = *(const float4*)(wr + kb + 4);
                float4 w2 = *(const float4*)(wr + kb + 8);
                float4 w3 = *(const float4*)(wr + kb + 12);
                float wv[16] = {w0.x, w0.y, w0.z, w0.w, w1.x, w1.y, w1.z, w1.w,
                                w2.x, w2.y, w2.z, w2.w, w3.x, w3.y, w3.z, w3.w};
#pragma unroll
                for (int kk = 0; kk < 16; kk++)
#pragma unroll
                    for (int t = 0; t < T_STEPS; t++)
                        hacc[t] = fmaf(wv[kk], sF[t * KC + kb + kk], hacc[t]);
            }
        }
    }

    if (o >= 0) {
#pragma unroll
        for (int t = 0; t < T_STEPS; t++)
            U[((size_t)t * NB + n) * Odim + o] = hacc[t];
    }
}

// ---------------------------------------------------------------------------
// Final: IF over U3, dot W_out, + b_out, cumsum (verbatim R1).
// ---------------------------------------------------------------------------
__global__ void final_kernel(const float* __restrict__ Wout,
                             const float* __restrict__ bout,
                             float* __restrict__ out)
{
    int n = blockIdx.x;
    int f = threadIdx.x;
    __shared__ float red[16];
    float v   = 0.f;
    float wf  = Wout[f];
    float acc = 0.f;
    float b   = bout[0];
    int lane = f & 31, wid = f >> 5;
    for (int t = 0; t < T_STEPS; t++) {
        v += g_U3[((size_t)t * NB + n) * F3DIM + f];
        float s = (v >= 1.0f) ? 1.0f : 0.0f;
        v = (v >= 1.0f) ? 0.0f : v;
        float p = wf * s;
#pragma unroll
        for (int off = 16; off; off >>= 1)
            p += __shfl_xor_sync(0xffffffffu, p, off);
        if (lane == 0) red[wid] = p;
        __syncthreads();
        if (f < 16) {
            float q = red[f];
#pragma unroll
            for (int off = 8; off; off >>= 1)
                q += __shfl_xor_sync(0x0000ffffu, q, off);
            if (f == 0) {
                acc += q + b;
                out[t * NB + n] = acc;
            }
        }
        __syncthreads();
    }
}

// ---------------------------------------------------------------------------
extern "C" void kernel_launch(void* const* d_in, const int* in_sizes, int n_in,
                              void* d_out, int out_size)
{
    (void)in_sizes; (void)n_in; (void)out_size;
    const float* x     = (const float*)d_in[0];
    const float* wjeff = (const float*)d_in[1];
    const float* wcc   = (const float*)d_in[2];
    const float* wsf0  = (const float*)d_in[3];
    const float* W1    = (const float*)d_in[4];
    const float* wsf1  = (const float*)d_in[5];
    const float* W2    = (const float*)d_in[6];
    const float* wsf2  = (const float*)d_in[7];
    const float* W3    = (const float*)d_in[8];
    const float* wsf3  = (const float*)d_in[9];
    const float* Wout  = (const float*)d_in[10];
    const float* bout  = (const float*)d_in[11];
    float* out = (float*)d_out;

    __nv_bfloat16 *A1, *A2, *A3, *W1s, *W2s, *W3s;
    float *F1, *F2, *F3, *U1, *U2, *U3;
    int *c1, *c2, *c3, *l1, *l2, *l3;
    cudaGetSymbolAddress((void**)&A1, g_A1s);
    cudaGetSymbolAddress((void**)&A2, g_A2s);
    cudaGetSymbolAddress((void**)&A3, g_A3s);
    cudaGetSymbolAddress((void**)&F1, g_F1);
    cudaGetSymbolAddress((void**)&F2, g_F2);
    cudaGetSymbolAddress((void**)&F3, g_F3);
    cudaGetSymbolAddress((void**)&U1, g_U1);
    cudaGetSymbolAddress((void**)&U2, g_U2);
    cudaGetSymbolAddress((void**)&U3, g_U3);
    cudaGetSymbolAddress((void**)&W1s, g_W1s);
    cudaGetSymbolAddress((void**)&W2s, g_W2s);
    cudaGetSymbolAddress((void**)&W3s, g_W3s);
    cudaGetSymbolAddress((void**)&c1, g_cnt1);
    cudaGetSymbolAddress((void**)&c2, g_cnt2);
    cudaGetSymbolAddress((void**)&c3, g_cnt3);
    cudaGetSymbolAddress((void**)&l1, g_lst1);
    cudaGetSymbolAddress((void**)&l2, g_lst2);
    cudaGetSymbolAddress((void**)&l3, g_lst3);

    cudaFuncSetAttribute(gemm3_kernel,
                         cudaFuncAttributeMaxDynamicSharedMemorySize, SMEM3);

    zero_counts<<<1, NB>>>();

    split_kernel<<<(F1DIM * CDIM + 255) / 256, 256>>>(W1, W1s, F1DIM * CDIM);
    split_kernel<<<(F2DIM * F1DIM + 255) / 256, 256>>>(W2, W2s, F2DIM * F1DIM);
    split_kernel<<<(F3DIM * F2DIM + 255) / 256, 256>>>(W3, W3s, F3DIM * F2DIM);

    stage1_kernel<<<(NB * CDIM * 32) / 256, 256>>>(x, wjeff, wcc, wsf0, wsf1);

    // Layer 1
    gemm3_kernel<<<dim3(F1DIM / 128, BATCH / 128), 256, SMEM3>>>(W1s, A1, U1, F1DIM, CDIM);
    flag_mid<<<(NB * F1DIM + 255) / 256, 256>>>(U1, A2, F2, wsf2, F1DIM, c1, l1);
    recompute_mid<<<dim3(NB, F1DIM / 256), 256>>>(W1, F1, c1, l1, A2, F2, wsf2, CDIM, F1DIM);

    // Layer 2
    gemm3_kernel<<<dim3(F2DIM / 128, BATCH / 128), 256, SMEM3>>>(W2s, A2, U2, F2DIM, F1DIM);
    flag_mid<<<(NB * F2DIM + 255) / 256, 256>>>(U2, A3, F3, wsf3, F2DIM, c2, l2);
    recompute_mid<<<dim3(NB, F2DIM / 256), 256>>>(W2, F2, c2, l2, A3, F3, wsf3, F1DIM, F2DIM);

    // Layer 3
    gemm3_kernel<<<dim3(F3DIM / 128, BATCH / 128), 256, SMEM3>>>(W3s, A3, U3, F3DIM, F2DIM);
    flag_last<<<(NB * F3DIM + 255) / 256, 256>>>(U3, F3DIM, c3, l3);
    recompute_last<<<dim3(NB, F3DIM / 256), 256>>>(W3, F3, c3, l3, U3, F2DIM, F3DIM);

    final_kernel<<<NB, F3DIM>>>(Wout, bout, out);
}

// round 16
// speedup vs baseline: 1.5940x; 1.1066x over previous
#include <cuda_runtime.h>
#include <cuda_bf16.h>
#include <math.h>
#include <stdint.h>

#define T_STEPS 32
#define NB      64
#define CDIM    512
#define F1DIM   2048
#define F2DIM   1024
#define F3DIM   512
#define BATCH   (T_STEPS * NB)   // 2048

#define MARGIN 4e-3f             // certified decision margin

// ---------------- scratch (device globals; no allocation allowed) -------------
// binary spikes (bf16-exact) fed to GEMMs
__device__ __align__(16) __nv_bfloat16 g_S1[BATCH * CDIM];
__device__ __align__(16) __nv_bfloat16 g_S2[BATCH * F1DIM];
__device__ __align__(16) __nv_bfloat16 g_S3[BATCH * F2DIM];
__device__ __align__(16) float         g_S4[BATCH * F3DIM];   // final spikes
// exact fp32 filtered traces (inputs to exact recompute)
__device__ __align__(16) float g_F1[BATCH * CDIM];
__device__ __align__(16) float g_F2[BATCH * F1DIM];
__device__ __align__(16) float g_F3[BATCH * F2DIM];
// provisional GEMM outputs (W @ s)
__device__ __align__(16) float g_U1[BATCH * F1DIM];
__device__ __align__(16) float g_U2[BATCH * F2DIM];
__device__ __align__(16) float g_U3[BATCH * F3DIM];
// weight split planes [2][O][K]
__device__ __align__(16) __nv_bfloat16 g_W1s[2 * F1DIM * CDIM];
__device__ __align__(16) __nv_bfloat16 g_W2s[2 * F2DIM * F1DIM];
__device__ __align__(16) __nv_bfloat16 g_W3s[2 * F3DIM * F2DIM];
// flag lists
__device__ int g_cnt1[NB], g_cnt2[NB], g_cnt3[NB];
__device__ int g_lst1[NB * F1DIM], g_lst2[NB * F2DIM], g_lst3[NB * F3DIM];

__device__ __forceinline__ float sigmoid_acc(float w) {
    return 1.0f / (1.0f + expf(-w));
}
__device__ __forceinline__ void split2(float w, __nv_bfloat16& h, __nv_bfloat16& m) {
    h = __float2bfloat16(w);
    float r1 = w - __bfloat162float(h);
    m = __float2bfloat16(r1);
}

__global__ void zero_counts() {
    int i = threadIdx.x;
    if (i < NB) { g_cnt1[i] = 0; g_cnt2[i] = 0; g_cnt3[i] = 0; }
}

// ---------------------------------------------------------------------------
__global__ void split_kernel(const float* __restrict__ W,
                             __nv_bfloat16* __restrict__ dst, int n)
{
    int i = blockIdx.x * blockDim.x + threadIdx.x;
    if (i >= n) return;
    __nv_bfloat16 h, m;
    split2(W[i], h, m);
    dst[i] = h; dst[n + i] = m;
}

// ---------------------------------------------------------------------------
// Stage 1 (R1-exact math) -> spikes s1 (bf16 exact) + trace f1 (wsf1) fp32
// ---------------------------------------------------------------------------
__global__ void stage1_kernel(const float* __restrict__ x,
                              const float* __restrict__ w_jeff,
                              const float* __restrict__ w_cc,
                              const float* __restrict__ w_sf0,
                              const float* __restrict__ w_sf1)
{
    int gw   = (blockIdx.x * blockDim.x + threadIdx.x) >> 5;
    int lane = threadIdx.x & 31;
    if (gw >= NB * CDIM) return;
    int n = gw / CDIM;
    int c = gw - n * CDIM;

    float wj0 = w_jeff[lane * 2 + 0];
    float wj1 = w_jeff[lane * 2 + 1];
    float wcc = w_cc[lane];
    float d0  = 1.0f - sigmoid_acc(w_sf0[0]);
    float d1  = 1.0f - sigmoid_acc(w_sf1[0]);
    const float invlif = 1.0f / 1.5f;

    float yf0 = 0.f, yf1 = 0.f;
    float v = 0.f, g = 0.f, vI = 0.f, fo = 0.f;

    const float* xb = x + (size_t)n * 2 * CDIM + c;
#pragma unroll
    for (int t = 0; t < T_STEPS; t++) {
        float x0 = xb[(size_t)t * NB * 2 * CDIM];
        float x1 = xb[(size_t)t * NB * 2 * CDIM + CDIM];
        yf0 = 0.5f * yf0 + x0;
        yf1 = 0.5f * yf1 + x1;
        float u = wj0 * yf0 + wj1 * yf1;
        v = v + (u - v) * invlif;
        float s = (v >= 1.0f) ? 1.0f : 0.0f;
        v = (v >= 1.0f) ? 0.0f : v;
        g = d0 * g + s;
        float r = g * wcc;
#pragma unroll
        for (int off = 16; off; off >>= 1)
            r += __shfl_xor_sync(0xffffffffu, r, off);
        vI += r;
        float s1 = (vI >= 1.0f) ? 1.0f : 0.0f;
        vI = (vI >= 1.0f) ? 0.0f : vI;
        fo = d1 * fo + s1;
        size_t id = ((size_t)t * NB + n) * CDIM + c;
        if (lane == 0)      g_S1[id] = __float2bfloat16(s1);
        else if (lane == 1) g_F1[id] = fo;
    }
}

// ---------------------------------------------------------------------------
// 2-pair split-bf16 tensor GEMM on BINARY SPIKES (provisional):
// U[m][o] = sum_k (W0+W1)[o][k] * s[m][k]    (s exactly bf16)
// 3 tiles/chunk (S, W0, W1); 110.6 KB smem -> 2 CTAs/SM.
// ---------------------------------------------------------------------------
#define PAD_B      144
#define TILE_B     (128 * PAD_B)
#define STAGE_B    (3 * TILE_B)       // S, W0, W1
#define SMEM2      (2 * STAGE_B)      // 110592

static __device__ __forceinline__ uint32_t smem_u32(const void* p) {
    return (uint32_t)__cvta_generic_to_shared(p);
}
static __device__ __forceinline__ void cp16(uint32_t dst, const void* src) {
    asm volatile("cp.async.cg.shared.global [%0], [%1], 16;"
                 :: "r"(dst), "l"(src) : "memory");
}
static __device__ __forceinline__ uint32_t ld32(const char* p) {
    return *reinterpret_cast<const uint32_t*>(p);
}
static __device__ __forceinline__ void mma16816(float* c, const uint32_t* a,
                                                const uint32_t* b) {
    asm volatile(
        "mma.sync.aligned.m16n8k16.row.col.f32.bf16.bf16.f32 "
        "{%0,%1,%2,%3}, {%4,%5,%6,%7}, {%8,%9}, {%0,%1,%2,%3};"
        : "+f"(c[0]), "+f"(c[1]), "+f"(c[2]), "+f"(c[3])
        : "r"(a[0]), "r"(a[1]), "r"(a[2]), "r"(a[3]), "r"(b[0]), "r"(b[1]));
}

__global__ void __launch_bounds__(256, 2)
gemm2p_kernel(const __nv_bfloat16* __restrict__ Ws,
              const __nv_bfloat16* __restrict__ S,
              float* __restrict__ U, int N, int K)
{
    extern __shared__ __align__(16) char smem[];
    uint32_t sb = smem_u32(smem);

    int tid  = threadIdx.x;
    int wid  = tid >> 5;
    int lane = tid & 31;
    int wm   = wid & 1;
    int wn   = wid >> 1;
    int m0 = blockIdx.y * 128;
    int n0 = blockIdx.x * 128;
    int NC = K / 64;
    size_t NK = (size_t)N * K;

    float acc[4][4][4];
#pragma unroll
    for (int i = 0; i < 4; i++)
#pragma unroll
        for (int j = 0; j < 4; j++)
#pragma unroll
            for (int q2 = 0; q2 < 4; q2++) acc[i][j][q2] = 0.f;

    int lrow = tid >> 3;
    int lc16 = tid & 7;

    auto issue_load = [&](int c, int b) {
        int kk = c * 64;
        uint32_t base = sb + b * STAGE_B;
        // spike tile
        {
            const __nv_bfloat16* Ag = S + (size_t)m0 * K + kk;
#pragma unroll
            for (int p = 0; p < 4; p++) {
                int row = lrow + p * 32;
                uint32_t off = (uint32_t)row * PAD_B + lc16 * 16;
                cp16(base + off, Ag + (size_t)row * K + lc16 * 8);
            }
        }
        // weight planes
#pragma unroll
        for (int sp = 0; sp < 2; sp++) {
            const __nv_bfloat16* Bg = Ws + sp * NK + (size_t)n0 * K + kk;
            uint32_t Bt = base + (1 + sp) * TILE_B;
#pragma unroll
            for (int p = 0; p < 4; p++) {
                int row = lrow + p * 32;
                uint32_t off = (uint32_t)row * PAD_B + lc16 * 16;
                cp16(Bt + off, Bg + (size_t)row * K + lc16 * 8);
            }
        }
        asm volatile("cp.async.commit_group;" ::: "memory");
    };

    issue_load(0, 0);

    int g = lane >> 2;
    int q = lane & 3;

    for (int c = 0; c < NC; c++) {
        int buf = c & 1;
        if (c + 1 < NC) {
            issue_load(c + 1, buf ^ 1);
            asm volatile("cp.async.wait_group 1;" ::: "memory");
        } else {
            asm volatile("cp.async.wait_group 0;" ::: "memory");
        }
        __syncthreads();

        const char* Sb = smem + buf * STAGE_B;
#pragma unroll
        for (int ks = 0; ks < 4; ks++) {
            int kbyte = ks * 32 + q * 4;
            uint32_t a[4][4];
#pragma unroll
            for (int mi = 0; mi < 4; mi++) {
                const char* base = Sb + (size_t)(wm * 64 + mi * 16 + g) * PAD_B + kbyte;
                a[mi][0] = ld32(base);
                a[mi][1] = ld32(base + 8 * PAD_B);
                a[mi][2] = ld32(base + 16);
                a[mi][3] = ld32(base + 8 * PAD_B + 16);
            }
            // mid plane first, hi plane last (small-first accumulation)
#pragma unroll
            for (int sp = 1; sp >= 0; sp--) {
                const char* Bt = Sb + (1 + sp) * TILE_B;
#pragma unroll
                for (int ni = 0; ni < 4; ni++) {
                    uint32_t b[2];
                    const char* base = Bt + (size_t)(wn * 32 + ni * 8 + g) * PAD_B + kbyte;
                    b[0] = ld32(base);
                    b[1] = ld32(base + 16);
#pragma unroll
                    for (int mi = 0; mi < 4; mi++)
                        mma16816(acc[mi][ni], a[mi], b);
                }
            }
        }
        __syncthreads();
    }

    int erow = m0 + wm * 64 + g;
    int ecol = n0 + wn * 32 + q * 2;
#pragma unroll
    for (int mi = 0; mi < 4; mi++) {
#pragma unroll
        for (int ni = 0; ni < 4; ni++) {
            float* p0 = U + (size_t)(erow + mi * 16) * N + ecol + ni * 8;
            float* p1 = U + (size_t)(erow + mi * 16 + 8) * N + ecol + ni * 8;
            *reinterpret_cast<float2*>(p0) = make_float2(acc[mi][ni][0], acc[mi][ni][1]);
            *reinterpret_cast<float2*>(p1) = make_float2(acc[mi][ni][2], acc[mi][ni][3]);
        }
    }
}

// ---------------------------------------------------------------------------
// Flag + provisional path (mid layers): h[t] = d_rec*h[t-1] + U[t] (commuted
// filter), v += h, IF; flags |v-1| < MARGIN. Writes next spikes (bf16 exact)
// and next exact fp32 trace f_next = filter(d_next, s).
// ---------------------------------------------------------------------------
__global__ void flag_mid(const float* __restrict__ U,
                         __nv_bfloat16* __restrict__ Sn, float* __restrict__ Fn,
                         const float* __restrict__ w_sf_rec,
                         const float* __restrict__ w_sf_next,
                         int Odim, int* __restrict__ cnt, int* __restrict__ lst)
{
    int idx = blockIdx.x * blockDim.x + threadIdx.x;
    if (idx >= NB * Odim) return;
    int o = idx % Odim;
    int n = idx / Odim;
    float dr = 1.0f - sigmoid_acc(w_sf_rec[0]);
    float dn = 1.0f - sigmoid_acc(w_sf_next[0]);
    float h = 0.f, v = 0.f, f = 0.f;
    int flg = 0;
#pragma unroll
    for (int t = 0; t < T_STEPS; t++) {
        size_t id = ((size_t)t * NB + n) * Odim + o;
        h = dr * h + U[id];
        v += h;
        if (fabsf(v - 1.0f) < MARGIN) flg = 1;
        float s = (v >= 1.0f) ? 1.0f : 0.0f;
        v = (v >= 1.0f) ? 0.0f : v;
        f = dn * f + s;
        Sn[id] = __float2bfloat16(s);
        Fn[id] = f;
    }
    if (flg) {
        int slot = atomicAdd(&cnt[n], 1);
        lst[n * Odim + slot] = o;
    }
}

// Last layer: commuted recurrence + IF -> final spikes S4 (fp32)
__global__ void flag_last(const float* __restrict__ U, float* __restrict__ S4,
                          const float* __restrict__ w_sf_rec, int Odim,
                          int* __restrict__ cnt, int* __restrict__ lst)
{
    int idx = blockIdx.x * blockDim.x + threadIdx.x;
    if (idx >= NB * Odim) return;
    int o = idx % Odim;
    int n = idx / Odim;
    float dr = 1.0f - sigmoid_acc(w_sf_rec[0]);
    float h = 0.f, v = 0.f;
    int flg = 0;
#pragma unroll
    for (int t = 0; t < T_STEPS; t++) {
        size_t id = ((size_t)t * NB + n) * Odim + o;
        h = dr * h + U[id];
        v += h;
        if (fabsf(v - 1.0f) < MARGIN) flg = 1;
        float s = (v >= 1.0f) ? 1.0f : 0.0f;
        v = (v >= 1.0f) ? 0.0f : v;
        S4[id] = s;
    }
    if (flg) {
        int slot = atomicAdd(&cnt[n], 1);
        lst[n * Odim + slot] = o;
    }
}

// ---------------------------------------------------------------------------
// Exact recompute for flagged neurons (sequential-k fp32 chain; proven exact).
// ---------------------------------------------------------------------------
#define KC 128

__global__ void __launch_bounds__(256)
recompute_mid(const float* __restrict__ W, const float* __restrict__ Fin,
              const int* __restrict__ cnt, const int* __restrict__ lst,
              __nv_bfloat16* __restrict__ Sn, float* __restrict__ Fn,
              const float* __restrict__ w_sf_next, int Kdim, int Odim)
{
    __shared__ float sF[T_STEPS * KC];
    int n = blockIdx.x;
    int tid = threadIdx.x;
    int c = cnt[n];
    int base = blockIdx.y * 256;
    if (base >= c) return;
    int o = (base + tid < c) ? lst[n * Odim + base + tid] : -1;

    float hacc[T_STEPS];
#pragma unroll
    for (int t = 0; t < T_STEPS; t++) hacc[t] = 0.f;

    for (int k0 = 0; k0 < Kdim; k0 += KC) {
        __syncthreads();
        for (int i = tid; i < T_STEPS * KC; i += 256) {
            int t = i >> 7, kk = i & (KC - 1);
            sF[i] = Fin[((size_t)t * NB + n) * Kdim + k0 + kk];
        }
        __syncthreads();
        if (o >= 0) {
            const float* wr = W + (size_t)o * Kdim + k0;
            for (int kb = 0; kb < KC; kb += 16) {
                float4 w0 = *(const float4*)(wr + kb);
                float4 w1 = *(const float4*)(wr + kb + 4);
                float4 w2 = *(const float4*)(wr + kb + 8);
                float4 w3 = *(const float4*)(wr + kb + 12);
                float wv[16] = {w0.x, w0.y, w0.z, w0.w, w1.x, w1.y, w1.z, w1.w,
                                w2.x, w2.y, w2.z, w2.w, w3.x, w3.y, w3.z, w3.w};
#pragma unroll
                for (int kk = 0; kk < 16; kk++)
#pragma unroll
                    for (int t = 0; t < T_STEPS; t++)
                        hacc[t] = fmaf(wv[kk], sF[t * KC + kb + kk], hacc[t]);
            }
        }
    }

    if (o >= 0) {
        float dn = 1.0f - sigmoid_acc(w_sf_next[0]);
        float v = 0.f, f = 0.f;
#pragma unroll
        for (int t = 0; t < T_STEPS; t++) {
            v += hacc[t];
            float s = (v >= 1.0f) ? 1.0f : 0.0f;
            v = (v >= 1.0f) ? 0.0f : v;
            f = dn * f + s;
            size_t id = ((size_t)t * NB + n) * Odim + o;
            Sn[id] = __float2bfloat16(s);
            Fn[id] = f;
        }
    }
}

__global__ void __launch_bounds__(256)
recompute_last(const float* __restrict__ W, const float* __restrict__ Fin,
               const int* __restrict__ cnt, const int* __restrict__ lst,
               float* __restrict__ S4, int Kdim, int Odim)
{
    __shared__ float sF[T_STEPS * KC];
    int n = blockIdx.x;
    int tid = threadIdx.x;
    int c = cnt[n];
    int base = blockIdx.y * 256;
    if (base >= c) return;
    int o = (base + tid < c) ? lst[n * Odim + base + tid] : -1;

    float hacc[T_STEPS];
#pragma unroll
    for (int t = 0; t < T_STEPS; t++) hacc[t] = 0.f;

    for (int k0 = 0; k0 < Kdim; k0 += KC) {
        __syncthreads();
        for (int i = tid; i < T_STEPS * KC; i += 256) {
            int t = i >> 7, kk = i & (KC - 1);
            sF[i] = Fin[((size_t)t * NB + n) * Kdim + k0 + kk];
        }
        __syncthreads();
        if (o >= 0) {
            const float* wr = W + (size_t)o * Kdim + k0;
            for (int kb = 0; kb < KC; kb += 16) {
                float4 w0 = *(const float4*)(wr + kb);
                float4 w1 = *(const float4*)(wr + kb + 4);
                float4 w2 = *(const float4*)(wr + kb + 8);
                float4 w3 = *(const float4*)(wr + kb + 12);
                float wv[16] = {w0.x, w0.y, w0.z, w0.w, w1.x, w1.y, w1.z, w1.w,
                                w2.x, w2.y, w2.z, w2.w, w3.x, w3.y, w3.z, w3.w};
#pragma unroll
                for (int kk = 0; kk < 16; kk++)
#pragma unroll
                    for (int t = 0; t < T_STEPS; t++)
                        hacc[t] = fmaf(wv[kk], sF[t * KC + kb + kk], hacc[t]);
            }
        }
    }

    if (o >= 0) {
        float v = 0.f;
#pragma unroll
        for (int t = 0; t < T_STEPS; t++) {
            v += hacc[t];
            float s = (v >= 1.0f) ? 1.0f : 0.0f;
            v = (v >= 1.0f) ? 0.0f : v;
            S4[((size_t)t * NB + n) * Odim + o] = s;
        }
    }
}

// ---------------------------------------------------------------------------
// Final: dot W_out with exact spikes S4, + b_out, cumsum over t.
// ---------------------------------------------------------------------------
__global__ void final_kernel(const float* __restrict__ Wout,
                             const float* __restrict__ bout,
                             const float* __restrict__ S4,
                             float* __restrict__ out)
{
    int n = blockIdx.x;
    int f = threadIdx.x;
    __shared__ float red[16];
    float wf  = Wout[f];
    float acc = 0.f;
    float b   = bout[0];
    int lane = f & 31, wid = f >> 5;
    for (int t = 0; t < T_STEPS; t++) {
        float p = wf * S4[((size_t)t * NB + n) * F3DIM + f];
#pragma unroll
        for (int off = 16; off; off >>= 1)
            p += __shfl_xor_sync(0xffffffffu, p, off);
        if (lane == 0) red[wid] = p;
        __syncthreads();
        if (f < 16) {
            float q = red[f];
#pragma unroll
            for (int off = 8; off; off >>= 1)
                q += __shfl_xor_sync(0x0000ffffu, q, off);
            if (f == 0) {
                acc += q + b;
                out[t * NB + n] = acc;
            }
        }
        __syncthreads();
    }
}

// ---------------------------------------------------------------------------
extern "C" void kernel_launch(void* const* d_in, const int* in_sizes, int n_in,
                              void* d_out, int out_size)
{
    (void)in_sizes; (void)n_in; (void)out_size;
    const float* x     = (const float*)d_in[0];
    const float* wjeff = (const float*)d_in[1];
    const float* wcc   = (const float*)d_in[2];
    const float* wsf0  = (const float*)d_in[3];
    const float* W1    = (const float*)d_in[4];
    const float* wsf1  = (const float*)d_in[5];
    const float* W2    = (const float*)d_in[6];
    const float* wsf2  = (const float*)d_in[7];
    const float* W3    = (const float*)d_in[8];
    const float* wsf3  = (const float*)d_in[9];
    const float* Wout  = (const float*)d_in[10];
    const float* bout  = (const float*)d_in[11];
    float* out = (float*)d_out;

    __nv_bfloat16 *S1, *S2, *S3, *W1s, *W2s, *W3s;
    float *S4, *F1, *F2, *F3, *U1, *U2, *U3;
    int *c1, *c2, *c3, *l1, *l2, *l3;
    cudaGetSymbolAddress((void**)&S1, g_S1);
    cudaGetSymbolAddress((void**)&S2, g_S2);
    cudaGetSymbolAddress((void**)&S3, g_S3);
    cudaGetSymbolAddress((void**)&S4, g_S4);
    cudaGetSymbolAddress((void**)&F1, g_F1);
    cudaGetSymbolAddress((void**)&F2, g_F2);
    cudaGetSymbolAddress((void**)&F3, g_F3);
    cudaGetSymbolAddress((void**)&U1, g_U1);
    cudaGetSymbolAddress((void**)&U2, g_U2);
    cudaGetSymbolAddress((void**)&U3, g_U3);
    cudaGetSymbolAddress((void**)&W1s, g_W1s);
    cudaGetSymbolAddress((void**)&W2s, g_W2s);
    cudaGetSymbolAddress((void**)&W3s, g_W3s);
    cudaGetSymbolAddress((void**)&c1, g_cnt1);
    cudaGetSymbolAddress((void**)&c2, g_cnt2);
    cudaGetSymbolAddress((void**)&c3, g_cnt3);
    cudaGetSymbolAddress((void**)&l1, g_lst1);
    cudaGetSymbolAddress((void**)&l2, g_lst2);
    cudaGetSymbolAddress((void**)&l3, g_lst3);

    cudaFuncSetAttribute(gemm2p_kernel,
                         cudaFuncAttributeMaxDynamicSharedMemorySize, SMEM2);

    zero_counts<<<1, NB>>>();

    split_kernel<<<(F1DIM * CDIM + 255) / 256, 256>>>(W1, W1s, F1DIM * CDIM);
    split_kernel<<<(F2DIM * F1DIM + 255) / 256, 256>>>(W2, W2s, F2DIM * F1DIM);
    split_kernel<<<(F3DIM * F2DIM + 255) / 256, 256>>>(W3, W3s, F3DIM * F2DIM);

    stage1_kernel<<<(NB * CDIM * 32) / 256, 256>>>(x, wjeff, wcc, wsf0, wsf1);

    // Layer 1: U1 = W1 @ s1 (provisional); h recurrence uses wsf1
    gemm2p_kernel<<<dim3(F1DIM / 128, BATCH / 128), 256, SMEM2>>>(W1s, S1, U1, F1DIM, CDIM);
    flag_mid<<<(NB * F1DIM + 255) / 256, 256>>>(U1, S2, F2, wsf1, wsf2, F1DIM, c1, l1);
    recompute_mid<<<dim3(NB, F1DIM / 256), 256>>>(W1, F1, c1, l1, S2, F2, wsf2, CDIM, F1DIM);

    // Layer 2
    gemm2p_kernel<<<dim3(F2DIM / 128, BATCH / 128), 256, SMEM2>>>(W2s, S2, U2, F2DIM, F1DIM);
    flag_mid<<<(NB * F2DIM + 255) / 256, 256>>>(U2, S3, F3, wsf2, wsf3, F2DIM, c2, l2);
    recompute_mid<<<dim3(NB, F2DIM / 256), 256>>>(W2, F2, c2, l2, S3, F3, wsf3, F1DIM, F2DIM);

    // Layer 3
    gemm2p_kernel<<<dim3(F3DIM / 128, BATCH / 128), 256, SMEM2>>>(W3s, S3, U3, F3DIM, F2DIM);
    flag_last<<<(NB * F3DIM + 255) / 256, 256>>>(U3, S4, wsf3, F3DIM, c3, l3);
    recompute_last<<<dim3(NB, F3DIM / 256), 256>>>(W3, F3, c3, l3, S4, F2DIM, F3DIM);

    final_kernel<<<NB, F3DIM>>>(Wout, bout, S4, out);
}

// round 17
// speedup vs baseline: 1.6636x; 1.0437x over previous
#include <cuda_runtime.h>
#include <cuda_bf16.h>
#include <math.h>
#include <stdint.h>

#define T_STEPS 32
#define NB      64
#define CDIM    512
#define F1DIM   2048
#define F2DIM   1024
#define F3DIM   512
#define BATCH   (T_STEPS * NB)   // 2048

#define MARGIN 4e-3f             // certified decision margin

// ---------------- scratch (device globals; no allocation allowed) -------------
__device__ __align__(16) __nv_bfloat16 g_S1[BATCH * CDIM];
__device__ __align__(16) __nv_bfloat16 g_S2[BATCH * F1DIM];
__device__ __align__(16) __nv_bfloat16 g_S3[BATCH * F2DIM];
__device__ __align__(16) float         g_S4[BATCH * F3DIM];
__device__ __align__(16) float g_F1[BATCH * CDIM];
__device__ __align__(16) float g_F2[BATCH * F1DIM];
__device__ __align__(16) float g_F3[BATCH * F2DIM];
__device__ __align__(16) float g_U1[BATCH * F1DIM];
__device__ __align__(16) float g_U2[BATCH * F2DIM];
__device__ __align__(16) float g_U3[BATCH * F3DIM];
__device__ __align__(16) __nv_bfloat16 g_W1s[2 * F1DIM * CDIM];
__device__ __align__(16) __nv_bfloat16 g_W2s[2 * F2DIM * F1DIM];
__device__ __align__(16) __nv_bfloat16 g_W3s[2 * F3DIM * F2DIM];
__device__ int g_cnt1[NB], g_cnt2[NB], g_cnt3[NB];
__device__ int g_lst1[NB * F1DIM], g_lst2[NB * F2DIM], g_lst3[NB * F3DIM];

__device__ __forceinline__ float sigmoid_acc(float w) {
    return 1.0f / (1.0f + expf(-w));
}
__device__ __forceinline__ void split2(float w, __nv_bfloat16& h, __nv_bfloat16& m) {
    h = __float2bfloat16(w);
    float r1 = w - __bfloat162float(h);
    m = __float2bfloat16(r1);
}

__global__ void zero_counts() {
    int i = threadIdx.x;
    if (i < NB) { g_cnt1[i] = 0; g_cnt2[i] = 0; g_cnt3[i] = 0; }
}

// ---------------------------------------------------------------------------
__global__ void split_kernel(const float* __restrict__ W,
                             __nv_bfloat16* __restrict__ dst, int n)
{
    int i = blockIdx.x * blockDim.x + threadIdx.x;
    if (i >= n) return;
    __nv_bfloat16 h, m;
    split2(W[i], h, m);
    dst[i] = h; dst[n + i] = m;
}

// ---------------------------------------------------------------------------
// Stage 1 (R1-exact math) -> spikes s1 (bf16 exact) + trace f1 (wsf1) fp32
// ---------------------------------------------------------------------------
__global__ void stage1_kernel(const float* __restrict__ x,
                              const float* __restrict__ w_jeff,
                              const float* __restrict__ w_cc,
                              const float* __restrict__ w_sf0,
                              const float* __restrict__ w_sf1)
{
    int gw   = (blockIdx.x * blockDim.x + threadIdx.x) >> 5;
    int lane = threadIdx.x & 31;
    if (gw >= NB * CDIM) return;
    int n = gw / CDIM;
    int c = gw - n * CDIM;

    float wj0 = w_jeff[lane * 2 + 0];
    float wj1 = w_jeff[lane * 2 + 1];
    float wcc = w_cc[lane];
    float d0  = 1.0f - sigmoid_acc(w_sf0[0]);
    float d1  = 1.0f - sigmoid_acc(w_sf1[0]);
    const float invlif = 1.0f / 1.5f;

    float yf0 = 0.f, yf1 = 0.f;
    float v = 0.f, g = 0.f, vI = 0.f, fo = 0.f;

    const float* xb = x + (size_t)n * 2 * CDIM + c;
#pragma unroll
    for (int t = 0; t < T_STEPS; t++) {
        float x0 = xb[(size_t)t * NB * 2 * CDIM];
        float x1 = xb[(size_t)t * NB * 2 * CDIM + CDIM];
        yf0 = 0.5f * yf0 + x0;
        yf1 = 0.5f * yf1 + x1;
        float u = wj0 * yf0 + wj1 * yf1;
        v = v + (u - v) * invlif;
        float s = (v >= 1.0f) ? 1.0f : 0.0f;
        v = (v >= 1.0f) ? 0.0f : v;
        g = d0 * g + s;
        float r = g * wcc;
#pragma unroll
        for (int off = 16; off; off >>= 1)
            r += __shfl_xor_sync(0xffffffffu, r, off);
        vI += r;
        float s1 = (vI >= 1.0f) ? 1.0f : 0.0f;
        vI = (vI >= 1.0f) ? 0.0f : vI;
        fo = d1 * fo + s1;
        size_t id = ((size_t)t * NB + n) * CDIM + c;
        if (lane == 0)      g_S1[id] = __float2bfloat16(s1);
        else if (lane == 1) g_F1[id] = fo;
    }
}

// ---------------------------------------------------------------------------
// 2-pair split-bf16 tensor GEMM on BINARY SPIKES, SW128 swizzle + ldmatrix.x4
// (fragment path verified: R3 == R4 bit-identical).
// U[m][o] = sum_k (W0+W1)[o][k] * s[m][k]
// Tiles: 128(m) x 128(o), BK=64. 3 x 16KB tiles per stage, double buffered.
// ---------------------------------------------------------------------------
#define TILE_SW  16384                 // 128 rows x 128 bytes (64 bf16)
#define STAGE_SW (3 * TILE_SW)         // S, W0(hi), W1(mid)
#define SMEMSW   (2 * STAGE_SW)        // 98304

static __device__ __forceinline__ uint32_t smem_u32(const void* p) {
    return (uint32_t)__cvta_generic_to_shared(p);
}
static __device__ __forceinline__ void cp16(uint32_t dst, const void* src) {
    asm volatile("cp.async.cg.shared.global [%0], [%1], 16;"
                 :: "r"(dst), "l"(src) : "memory");
}
static __device__ __forceinline__ void ldsm_x4(uint32_t* r, uint32_t addr) {
    asm volatile("ldmatrix.sync.aligned.m8n8.x4.shared.b16 {%0,%1,%2,%3}, [%4];"
                 : "=r"(r[0]), "=r"(r[1]), "=r"(r[2]), "=r"(r[3]) : "r"(addr));
}
static __device__ __forceinline__ void mma16816(float* c, const uint32_t* a,
                                                const uint32_t* b) {
    asm volatile(
        "mma.sync.aligned.m16n8k16.row.col.f32.bf16.bf16.f32 "
        "{%0,%1,%2,%3}, {%4,%5,%6,%7}, {%8,%9}, {%0,%1,%2,%3};"
        : "+f"(c[0]), "+f"(c[1]), "+f"(c[2]), "+f"(c[3])
        : "r"(a[0]), "r"(a[1]), "r"(a[2]), "r"(a[3]), "r"(b[0]), "r"(b[1]));
}

__global__ void __launch_bounds__(256, 2)
gemm2p_kernel(const __nv_bfloat16* __restrict__ Ws,
              const __nv_bfloat16* __restrict__ S,
              float* __restrict__ U, int N, int K)
{
    extern __shared__ __align__(1024) char smem[];
    uint32_t sb = smem_u32(smem);

    int tid  = threadIdx.x;
    int wid  = tid >> 5;
    int lane = tid & 31;
    int wm   = wid & 1;        // 2 warps along m (64 rows each)
    int wn   = wid >> 1;       // 4 warps along o (32 cols each)
    int m0 = blockIdx.y * 128;
    int n0 = blockIdx.x * 128;
    int NC = K / 64;
    size_t NK = (size_t)N * K;

    float acc[4][4][4];
#pragma unroll
    for (int i = 0; i < 4; i++)
#pragma unroll
        for (int j = 0; j < 4; j++)
#pragma unroll
            for (int q2 = 0; q2 < 4; q2++) acc[i][j][q2] = 0.f;

    int lrow = tid >> 3;       // 0..31
    int lc16 = tid & 7;

    auto issue_load = [&](int c, int b) {
        int kk = c * 64;
        uint32_t base = sb + b * STAGE_SW;
        const __nv_bfloat16* Ag = S + (size_t)m0 * K + kk;
        const __nv_bfloat16* B0 = Ws + (size_t)n0 * K + kk;           // hi
        const __nv_bfloat16* B1 = Ws + NK + (size_t)n0 * K + kk;      // mid
#pragma unroll
        for (int p = 0; p < 4; p++) {
            int row = lrow + p * 32;
            uint32_t off = (uint32_t)row * 128 + ((lc16 ^ (row & 7)) << 4);
            cp16(base + off,               Ag + (size_t)row * K + lc16 * 8);
            cp16(base + TILE_SW + off,     B0 + (size_t)row * K + lc16 * 8);
            cp16(base + 2 * TILE_SW + off, B1 + (size_t)row * K + lc16 * 8);
        }
        asm volatile("cp.async.commit_group;" ::: "memory");
    };

    issue_load(0, 0);

    int arow = wm * 64 + (lane & 15);
    int asw  = (arow & 7);
    int brow = wn * 32 + ((lane >> 4) << 3) + (lane & 7);
    int bsw  = (brow & 7);

    for (int c = 0; c < NC; c++) {
        int buf = c & 1;
        if (c + 1 < NC) {
            issue_load(c + 1, buf ^ 1);
            asm volatile("cp.async.wait_group 1;" ::: "memory");
        } else {
            asm volatile("cp.async.wait_group 0;" ::: "memory");
        }
        __syncthreads();

        uint32_t Ab = sb + buf * STAGE_SW;
#pragma unroll
        for (int ks = 0; ks < 4; ks++) {
            uint32_t a[4][4];
            int ac16 = 2 * ks + (lane >> 4);
            uint32_t ax = (uint32_t)((ac16 ^ asw) << 4);
#pragma unroll
            for (int mi = 0; mi < 4; mi++)
                ldsm_x4(a[mi], Ab + (uint32_t)(arow + mi * 16) * 128 + ax);

            int bc16 = 2 * ks + ((lane >> 3) & 1);
            uint32_t bx = (uint32_t)((bc16 ^ bsw) << 4);
            // mid plane first (smaller terms), hi plane last
#pragma unroll
            for (int sp = 1; sp >= 0; sp--) {
                uint32_t Bp = Ab + (1 + sp) * TILE_SW;
                uint32_t b[4][2];
#pragma unroll
                for (int np = 0; np < 2; np++) {
                    uint32_t r[4];
                    ldsm_x4(r, Bp + (uint32_t)(brow + np * 16) * 128 + bx);
                    b[2 * np][0] = r[0]; b[2 * np][1] = r[1];
                    b[2 * np + 1][0] = r[2]; b[2 * np + 1][1] = r[3];
                }
#pragma unroll
                for (int mi = 0; mi < 4; mi++)
#pragma unroll
                    for (int ni = 0; ni < 4; ni++)
                        mma16816(acc[mi][ni], a[mi], b[ni]);
            }
        }
        __syncthreads();
    }

    int g = lane >> 2;
    int q = lane & 3;
    int erow = m0 + wm * 64 + g;
    int ecol = n0 + wn * 32 + q * 2;
#pragma unroll
    for (int mi = 0; mi < 4; mi++) {
#pragma unroll
        for (int ni = 0; ni < 4; ni++) {
            float* p0 = U + (size_t)(erow + mi * 16) * N + ecol + ni * 8;
            float* p1 = U + (size_t)(erow + mi * 16 + 8) * N + ecol + ni * 8;
            *reinterpret_cast<float2*>(p0) = make_float2(acc[mi][ni][0], acc[mi][ni][1]);
            *reinterpret_cast<float2*>(p1) = make_float2(acc[mi][ni][2], acc[mi][ni][3]);
        }
    }
}

// ---------------------------------------------------------------------------
// Flag + provisional path (mid layers): commuted filter + IF, flag |v-1|<MARGIN.
// ---------------------------------------------------------------------------
__global__ void flag_mid(const float* __restrict__ U,
                         __nv_bfloat16* __restrict__ Sn, float* __restrict__ Fn,
                         const float* __restrict__ w_sf_rec,
                         const float* __restrict__ w_sf_next,
                         int Odim, int* __restrict__ cnt, int* __restrict__ lst)
{
    int idx = blockIdx.x * blockDim.x + threadIdx.x;
    if (idx >= NB * Odim) return;
    int o = idx % Odim;
    int n = idx / Odim;
    float dr = 1.0f - sigmoid_acc(w_sf_rec[0]);
    float dn = 1.0f - sigmoid_acc(w_sf_next[0]);
    float h = 0.f, v = 0.f, f = 0.f;
    int flg = 0;
#pragma unroll
    for (int t = 0; t < T_STEPS; t++) {
        size_t id = ((size_t)t * NB + n) * Odim + o;
        h = dr * h + U[id];
        v += h;
        if (fabsf(v - 1.0f) < MARGIN) flg = 1;
        float s = (v >= 1.0f) ? 1.0f : 0.0f;
        v = (v >= 1.0f) ? 0.0f : v;
        f = dn * f + s;
        Sn[id] = __float2bfloat16(s);
        Fn[id] = f;
    }
    if (flg) {
        int slot = atomicAdd(&cnt[n], 1);
        lst[n * Odim + slot] = o;
    }
}

__global__ void flag_last(const float* __restrict__ U, float* __restrict__ S4,
                          const float* __restrict__ w_sf_rec, int Odim,
                          int* __restrict__ cnt, int* __restrict__ lst)
{
    int idx = blockIdx.x * blockDim.x + threadIdx.x;
    if (idx >= NB * Odim) return;
    int o = idx % Odim;
    int n = idx / Odim;
    float dr = 1.0f - sigmoid_acc(w_sf_rec[0]);
    float h = 0.f, v = 0.f;
    int flg = 0;
#pragma unroll
    for (int t = 0; t < T_STEPS; t++) {
        size_t id = ((size_t)t * NB + n) * Odim + o;
        h = dr * h + U[id];
        v += h;
        if (fabsf(v - 1.0f) < MARGIN) flg = 1;
        float s = (v >= 1.0f) ? 1.0f : 0.0f;
        v = (v >= 1.0f) ? 0.0f : v;
        S4[id] = s;
    }
    if (flg) {
        int slot = atomicAdd(&cnt[n], 1);
        lst[n * Odim + slot] = o;
    }
}

// ---------------------------------------------------------------------------
// Exact recompute for flagged neurons (sequential-k fp32 chain).
// ---------------------------------------------------------------------------
#define KC 128

__global__ void __launch_bounds__(256)
recompute_mid(const float* __restrict__ W, const float* __restrict__ Fin,
              const int* __restrict__ cnt, const int* __restrict__ lst,
              __nv_bfloat16* __restrict__ Sn, float* __restrict__ Fn,
              const float* __restrict__ w_sf_next, int Kdim, int Odim)
{
    __shared__ float sF[T_STEPS * KC];
    int n = blockIdx.x;
    int tid = threadIdx.x;
    int c = cnt[n];
    int base = blockIdx.y * 256;
    if (base >= c) return;
    int o = (base + tid < c) ? lst[n * Odim + base + tid] : -1;

    float hacc[T_STEPS];
#pragma unroll
    for (int t = 0; t < T_STEPS; t++) hacc[t] = 0.f;

    for (int k0 = 0; k0 < Kdim; k0 += KC) {
        __syncthreads();
        for (int i = tid; i < T_STEPS * KC; i += 256) {
            int t = i >> 7, kk = i & (KC - 1);
            sF[i] = Fin[((size_t)t * NB + n) * Kdim + k0 + kk];
        }
        __syncthreads();
        if (o >= 0) {
            const float* wr = W + (size_t)o * Kdim + k0;
            for (int kb = 0; kb < KC; kb += 16) {
                float4 w0 = *(const float4*)(wr + kb);
                float4 w1 = *(const float4*)(wr + kb + 4);
                float4 w2 = *(const float4*)(wr + kb + 8);
                float4 w3 = *(const float4*)(wr + kb + 12);
                float wv[16] = {w0.x, w0.y, w0.z, w0.w, w1.x, w1.y, w1.z, w1.w,
                                w2.x, w2.y, w2.z, w2.w, w3.x, w3.y, w3.z, w3.w};
#pragma unroll
                for (int kk = 0; kk < 16; kk++)
#pragma unroll
                    for (int t = 0; t < T_STEPS; t++)
                        hacc[t] = fmaf(wv[kk], sF[t * KC + kb + kk], hacc[t]);
            }
        }
    }

    if (o >= 0) {
        float dn = 1.0f - sigmoid_acc(w_sf_next[0]);
        float v = 0.f, f = 0.f;
#pragma unroll
        for (int t = 0; t < T_STEPS; t++) {
            v += hacc[t];
            float s = (v >= 1.0f) ? 1.0f : 0.0f;
            v = (v >= 1.0f) ? 0.0f : v;
            f = dn * f + s;
            size_t id = ((size_t)t * NB + n) * Odim + o;
            Sn[id] = __float2bfloat16(s);
            Fn[id] = f;
        }
    }
}

__global__ void __launch_bounds__(256)
recompute_last(const float* __restrict__ W, const float* __restrict__ Fin,
               const int* __restrict__ cnt, const int* __restrict__ lst,
               float* __restrict__ S4, int Kdim, int Odim)
{
    __shared__ float sF[T_STEPS * KC];
    int n = blockIdx.x;
    int tid = threadIdx.x;
    int c = cnt[n];
    int base = blockIdx.y * 256;
    if (base >= c) return;
    int o = (base + tid < c) ? lst[n * Odim + base + tid] : -1;

    float hacc[T_STEPS];
#pragma unroll
    for (int t = 0; t < T_STEPS; t++) hacc[t] = 0.f;

    for (int k0 = 0; k0 < Kdim; k0 += KC) {
        __syncthreads();
        for (int i = tid; i < T_STEPS * KC; i += 256) {
            int t = i >> 7, kk = i & (KC - 1);
            sF[i] = Fin[((size_t)t * NB + n) * Kdim + k0 + kk];
        }
        __syncthreads();
        if (o >= 0) {
            const float* wr = W + (size_t)o * Kdim + k0;
            for (int kb = 0; kb < KC; kb += 16) {
                float4 w0 = *(const float4*)(wr + kb);
                float4 w1 = *(const float4*)(wr + kb + 4);
                float4 w2 = *(const float4*)(wr + kb + 8);
                float4 w3 = *(const float4*)(wr + kb + 12);
                float wv[16] = {w0.x, w0.y, w0.z, w0.w, w1.x, w1.y, w1.z, w1.w,
                                w2.x, w2.y, w2.z, w2.w, w3.x, w3.y, w3.z, w3.w};
#pragma unroll
                for (int kk = 0; kk < 16; kk++)
#pragma unroll
                    for (int t = 0; t < T_STEPS; t++)
                        hacc[t] = fmaf(wv[kk], sF[t * KC + kb + kk], hacc[t]);
            }
        }
    }

    if (o >= 0) {
        float v = 0.f;
#pragma unroll
        for (int t = 0; t < T_STEPS; t++) {
            v += hacc[t];
            float s = (v >= 1.0f) ? 1.0f : 0.0f;
            v = (v >= 1.0f) ? 0.0f : v;
            S4[((size_t)t * NB + n) * Odim + o] = s;
        }
    }
}

// ---------------------------------------------------------------------------
// Final: dot W_out with exact spikes S4, + b_out, cumsum over t.
// ---------------------------------------------------------------------------
__global__ void final_kernel(const float* __restrict__ Wout,
                             const float* __restrict__ bout,
                             const float* __restrict__ S4,
                             float* __restrict__ out)
{
    int n = blockIdx.x;
    int f = threadIdx.x;
    __shared__ float red[16];
    float wf  = Wout[f];
    float acc = 0.f;
    float b   = bout[0];
    int lane = f & 31, wid = f >> 5;
    for (int t = 0; t < T_STEPS; t++) {
        float p = wf * S4[((size_t)t * NB + n) * F3DIM + f];
#pragma unroll
        for (int off = 16; off; off >>= 1)
            p += __shfl_xor_sync(0xffffffffu, p, off);
        if (lane == 0) red[wid] = p;
        __syncthreads();
        if (f < 16) {
            float q = red[f];
#pragma unroll
            for (int off = 8; off; off >>= 1)
                q += __shfl_xor_sync(0x0000ffffu, q, off);
            if (f == 0) {
                acc += q + b;
                out[t * NB + n] = acc;
            }
        }
        __syncthreads();
    }
}

// ---------------------------------------------------------------------------
extern "C" void kernel_launch(void* const* d_in, const int* in_sizes, int n_in,
                              void* d_out, int out_size)
{
    (void)in_sizes; (void)n_in; (void)out_size;
    const float* x     = (const float*)d_in[0];
    const float* wjeff = (const float*)d_in[1];
    const float* wcc   = (const float*)d_in[2];
    const float* wsf0  = (const float*)d_in[3];
    const float* W1    = (const float*)d_in[4];
    const float* wsf1  = (const float*)d_in[5];
    const float* W2    = (const float*)d_in[6];
    const float* wsf2  = (const float*)d_in[7];
    const float* W3    = (const float*)d_in[8];
    const float* wsf3  = (const float*)d_in[9];
    const float* Wout  = (const float*)d_in[10];
    const float* bout  = (const float*)d_in[11];
    float* out = (float*)d_out;

    __nv_bfloat16 *S1, *S2, *S3, *W1s, *W2s, *W3s;
    float *S4, *F1, *F2, *F3, *U1, *U2, *U3;
    int *c1, *c2, *c3, *l1, *l2, *l3;
    cudaGetSymbolAddress((void**)&S1, g_S1);
    cudaGetSymbolAddress((void**)&S2, g_S2);
    cudaGetSymbolAddress((void**)&S3, g_S3);
    cudaGetSymbolAddress((void**)&S4, g_S4);
    cudaGetSymbolAddress((void**)&F1, g_F1);
    cudaGetSymbolAddress((void**)&F2, g_F2);
    cudaGetSymbolAddress((void**)&F3, g_F3);
    cudaGetSymbolAddress((void**)&U1, g_U1);
    cudaGetSymbolAddress((void**)&U2, g_U2);
    cudaGetSymbolAddress((void**)&U3, g_U3);
    cudaGetSymbolAddress((void**)&W1s, g_W1s);
    cudaGetSymbolAddress((void**)&W2s, g_W2s);
    cudaGetSymbolAddress((void**)&W3s, g_W3s);
    cudaGetSymbolAddress((void**)&c1, g_cnt1);
    cudaGetSymbolAddress((void**)&c2, g_cnt2);
    cudaGetSymbolAddress((void**)&c3, g_cnt3);
    cudaGetSymbolAddress((void**)&l1, g_lst1);
    cudaGetSymbolAddress((void**)&l2, g_lst2);
    cudaGetSymbolAddress((void**)&l3, g_lst3);

    cudaFuncSetAttribute(gemm2p_kernel,
                         cudaFuncAttributeMaxDynamicSharedMemorySize, SMEMSW);

    zero_counts<<<1, NB>>>();

    split_kernel<<<(F1DIM * CDIM + 255) / 256, 256>>>(W1, W1s, F1DIM * CDIM);
    split_kernel<<<(F2DIM * F1DIM + 255) / 256, 256>>>(W2, W2s, F2DIM * F1DIM);
    split_kernel<<<(F3DIM * F2DIM + 255) / 256, 256>>>(W3, W3s, F3DIM * F2DIM);

    stage1_kernel<<<(NB * CDIM * 32) / 256, 256>>>(x, wjeff, wcc, wsf0, wsf1);

    // Layer 1
    gemm2p_kernel<<<dim3(F1DIM / 128, BATCH / 128), 256, SMEMSW>>>(W1s, S1, U1, F1DIM, CDIM);
    flag_mid<<<(NB * F1DIM + 255) / 256, 256>>>(U1, S2, F2, wsf1, wsf2, F1DIM, c1, l1);
    recompute_mid<<<dim3(NB, F1DIM / 256), 256>>>(W1, F1, c1, l1, S2, F2, wsf2, CDIM, F1DIM);

    // Layer 2
    gemm2p_kernel<<<dim3(F2DIM / 128, BATCH / 128), 256, SMEMSW>>>(W2s, S2, U2, F2DIM, F1DIM);
    flag_mid<<<(NB * F2DIM + 255) / 256, 256>>>(U2, S3, F3, wsf2, wsf3, F2DIM, c2, l2);
    recompute_mid<<<dim3(NB, F2DIM / 256), 256>>>(W2, F2, c2, l2, S3, F3, wsf3, F1DIM, F2DIM);

    // Layer 3
    gemm2p_kernel<<<dim3(F3DIM / 128, BATCH / 128), 256, SMEMSW>>>(W3s, S3, U3, F3DIM, F2DIM);
    flag_last<<<(NB * F3DIM + 255) / 256, 256>>>(U3, S4, wsf3, F3DIM, c3, l3);
    recompute_last<<<dim3(NB, F3DIM / 256), 256>>>(W3, F3, c3, l3, S4, F2DIM, F3DIM);

    final_kernel<<<NB, F3DIM>>>(Wout, bout, S4, out);
}